// round 6
// baseline (speedup 1.0000x reference)
#include <cuda_runtime.h>
#include <cfloat>
#include <math.h>
#include <stdint.h>

// ---------------------------------------------------------------------------
// Problem constants
// ---------------------------------------------------------------------------
#define T_LEN   65536
#define DIM_S   64
#define DIM_A   8
#define DIM_C   16
#define HDIM    256
#define NTRANS  (T_LEN - 1)          // 65535 transitions
#define CHUNK   256                  // transitions per scan chunk
#define G_CHUNKS 256                 // ceil(65535 / 256)

// Output layout (floats), concatenated in reference return order:
// log_alpha [T,16], log_beta [T,16], log_trs [T-1,16,16], log_pis [T,16], entropy [T-1,16]
static const size_t OFF_ALPHA = 0;
static const size_t OFF_BETA  = (size_t)T_LEN * DIM_C;
static const size_t OFF_TRS   = 2ull * T_LEN * DIM_C;
static const size_t OFF_PIS   = OFF_TRS + (size_t)NTRANS * DIM_C * DIM_C;
static const size_t OFF_ENT   = OFF_PIS + (size_t)T_LEN * DIM_C;

// ---------------------------------------------------------------------------
// Device scratch (static __device__ arrays; no allocation APIs)
// ---------------------------------------------------------------------------
__device__ float g_buf1[(size_t)T_LEN * HDIM];            // 64 MB hidden 1
__device__ float g_buf2[(size_t)T_LEN * HDIM];            // 64 MB hidden 2
__device__ float g_mean[(size_t)T_LEN * (DIM_C * DIM_A)]; // 32 MB policy out
__device__ float g_logits[(size_t)T_LEN * ((DIM_C + 1) * DIM_C)]; // 71 MB obs out
__device__ float g_Cmat[G_CHUNKS * 256];                  // chunk transfer matrices
__device__ float g_Va[(G_CHUNKS + 1) * 16];               // alpha at chunk starts
__device__ float g_Wb[(G_CHUNKS + 1) * 16];               // beta  at chunk starts
__device__ float g_tr0[16];                               // log_trs_full[0, -1]

// ---------------------------------------------------------------------------
// SGEMM: C[T x N] = act(A[T x K] @ W[K x N] + b), fp32, 128x128x8 tiles
// ---------------------------------------------------------------------------
template <int K, int N, bool RELU>
__global__ __launch_bounds__(256) void gemm_kernel(
    const float* __restrict__ A, const float* __restrict__ W,
    const float* __restrict__ bias, float* __restrict__ C)
{
    constexpr int BM = 128, BN = 128, BK = 8;
    constexpr bool NG = (N % BN) != 0;   // needs column guards (N = 272)

    __shared__ float As[BK][BM + 4];
    __shared__ float Ws[BK][BN];

    const int tid  = threadIdx.x;
    const int row0 = blockIdx.x * BM;
    const int col0 = blockIdx.y * BN;
    const int tx   = tid & 15;    // 16 col groups of 8
    const int ty   = tid >> 4;    // 16 row groups of 8

    float acc[8][8];
#pragma unroll
    for (int i = 0; i < 8; i++)
#pragma unroll
        for (int j = 0; j < 8; j++) acc[i][j] = 0.f;

    const int a_m = tid >> 1;           // 0..127
    const int a_k = (tid & 1) * 4;      // 0 or 4
    const int w_k = tid >> 5;           // 0..7
    const int w_n = (tid & 31) * 4;     // 0..124

    for (int k0 = 0; k0 < K; k0 += BK) {
        float4 av = *reinterpret_cast<const float4*>(
            &A[(size_t)(row0 + a_m) * K + k0 + a_k]);
        float4 wv;
        if (!NG) {
            wv = *reinterpret_cast<const float4*>(
                &W[(size_t)(k0 + w_k) * N + col0 + w_n]);
        } else {
            const int cn = col0 + w_n;
            const size_t wb = (size_t)(k0 + w_k) * N;
            wv.x = (cn + 0 < N) ? W[wb + cn + 0] : 0.f;
            wv.y = (cn + 1 < N) ? W[wb + cn + 1] : 0.f;
            wv.z = (cn + 2 < N) ? W[wb + cn + 2] : 0.f;
            wv.w = (cn + 3 < N) ? W[wb + cn + 3] : 0.f;
        }
        As[a_k + 0][a_m] = av.x;
        As[a_k + 1][a_m] = av.y;
        As[a_k + 2][a_m] = av.z;
        As[a_k + 3][a_m] = av.w;
        *reinterpret_cast<float4*>(&Ws[w_k][w_n]) = wv;
        __syncthreads();

#pragma unroll
        for (int kk = 0; kk < BK; kk++) {
            float a[8], b[8];
            *reinterpret_cast<float4*>(&a[0]) =
                *reinterpret_cast<const float4*>(&As[kk][ty * 8]);
            *reinterpret_cast<float4*>(&a[4]) =
                *reinterpret_cast<const float4*>(&As[kk][ty * 8 + 4]);
            *reinterpret_cast<float4*>(&b[0]) =
                *reinterpret_cast<const float4*>(&Ws[kk][tx * 8]);
            *reinterpret_cast<float4*>(&b[4]) =
                *reinterpret_cast<const float4*>(&Ws[kk][tx * 8 + 4]);
#pragma unroll
            for (int i = 0; i < 8; i++)
#pragma unroll
                for (int j = 0; j < 8; j++)
                    acc[i][j] = fmaf(a[i], b[j], acc[i][j]);
        }
        __syncthreads();
    }

    float bb[8];
#pragma unroll
    for (int j = 0; j < 8; j++) {
        int cn = col0 + tx * 8 + j;
        bb[j] = (!NG || cn < N) ? bias[cn] : 0.f;
    }
#pragma unroll
    for (int i = 0; i < 8; i++) {
        const size_t r = (size_t)(row0 + ty * 8 + i);
#pragma unroll
        for (int j = 0; j < 8; j++) {
            int cn = col0 + tx * 8 + j;
            if (!NG || cn < N) {
                float v = acc[i][j] + bb[j];
                if (RELU) v = fmaxf(v, 0.f);
                C[r * N + cn] = v;
            }
        }
    }
}

// ---------------------------------------------------------------------------
// log_pis[t][c] = sum_a -0.5*((a - clip(mean))/std)^2 - logstd_a - 0.5*log(2pi)
// ---------------------------------------------------------------------------
__global__ void logpis_kernel(const float* __restrict__ mean,
                              const float* __restrict__ a_arr,
                              const float* __restrict__ a_log_std,
                              float* __restrict__ out_pis)
{
    __shared__ float s_inv_std[8];
    __shared__ float s_ls[8];
    if (threadIdx.x < 8) {
        float ls = tanhf(a_log_std[threadIdx.x]);
        ls = -5.0f + 3.5f * (ls + 1.0f);
        s_ls[threadIdx.x] = ls;
        s_inv_std[threadIdx.x] = expf(-ls);
    }
    __syncthreads();

    int idx = blockIdx.x * blockDim.x + threadIdx.x;
    if (idx >= T_LEN * DIM_C) return;

    float lsum = 0.f;
#pragma unroll
    for (int a = 0; a < 8; a++) lsum += s_ls[a];
    const float cst = -lsum - 4.0f * 1.8378770664093453f;  // 8 * 0.5*log(2pi)

    const int t = idx >> 4;
    const int c = idx & 15;
    const float* m  = mean + (size_t)t * 128 + c * 8;
    const float* av = a_arr + (size_t)t * 8;
    float s = 0.f;
#pragma unroll
    for (int a = 0; a < 8; a++) {
        float mm = fminf(fmaxf(m[a], -10.f), 10.f);
        float z = (av[a] - mm) * s_inv_std[a];
        s = fmaf(z, z, s);
    }
    out_pis[idx] = -0.5f * s + cst;
}

// ---------------------------------------------------------------------------
// log_softmax over groups of 16, plus entropy, plus log_tr0 extraction
// ---------------------------------------------------------------------------
__global__ void softmax_kernel(const float* __restrict__ logits,
                               float* __restrict__ out_trs,
                               float* __restrict__ out_ent,
                               float* __restrict__ tr0)
{
    int idx = blockIdx.x * blockDim.x + threadIdx.x;
    if (idx >= T_LEN * 17) return;
    const int t = idx / 17;
    const int g = idx - t * 17;
    const bool is0 = (t == 0 && g == 16);
    const bool isn = (t >= 1 && g < 16);
    if (!is0 && !isn) return;

    const float* row = logits + (size_t)t * 272 + g * 16;
    float v[16];
#pragma unroll
    for (int q = 0; q < 4; q++)
        *reinterpret_cast<float4*>(&v[q * 4]) =
            *reinterpret_cast<const float4*>(&row[q * 4]);

    float mx = v[0];
#pragma unroll
    for (int j = 1; j < 16; j++) mx = fmaxf(mx, v[j]);
    float s = 0.f, ws = 0.f;
#pragma unroll
    for (int j = 0; j < 16; j++) {
        float d = v[j] - mx;
        float e = __expf(d);
        s += e;
        ws = fmaf(d, e, ws);
    }
    const float ls  = __logf(s);
    const float lse = mx + ls;

    if (is0) {
#pragma unroll
        for (int j = 0; j < 16; j++) tr0[j] = v[j] - lse;
    } else {
        float* o = out_trs + (size_t)(t - 1) * 256 + g * 16;
#pragma unroll
        for (int j = 0; j < 16; j++) o[j] = v[j] - lse;
        // entropy = -(sum_j lt_j * exp(lt_j)) = ls - ws/s
        out_ent[(size_t)(t - 1) * 16 + g] = ls - ws / s;
    }
}

// ---------------------------------------------------------------------------
// Scan pass 1: per-chunk log-semiring transfer matrix
// C_g = M'_{t0} o M'_{t0+1} o ... ,  M'_t[i][j] = log_trs[t][i][j] + log_pis[t+1][j]
// One 256-thread CTA per chunk; thread (i,j) holds C[i][j].
// ---------------------------------------------------------------------------
__global__ __launch_bounds__(256) void pass1_kernel(
    const float* __restrict__ trs, const float* __restrict__ pis,
    float* __restrict__ Cmat)
{
    const int g   = blockIdx.x;
    const int tid = threadIdx.x;
    const int i   = tid >> 4;
    const int j   = tid & 15;
    const int t0  = g * CHUNK;
    const int t1  = min(t0 + CHUNK, NTRANS);

    __shared__ float Cs[2][256];
    __shared__ float Ms[256];

    Cs[0][tid] = trs[(size_t)t0 * 256 + tid] + pis[(size_t)(t0 + 1) * 16 + j];
    int cb = 0;

    for (int t = t0 + 1; t < t1; t++) {
        float mv = trs[(size_t)t * 256 + tid] + pis[(size_t)(t + 1) * 16 + j];
        __syncthreads();          // prior Ms reads done, Cs[cb] visible
        Ms[tid] = mv;
        __syncthreads();

        float tmp[16];
        float mx = -FLT_MAX;
#pragma unroll
        for (int k = 0; k < 16; k++) {
            tmp[k] = Cs[cb][i * 16 + k] + Ms[k * 16 + j];
            mx = fmaxf(mx, tmp[k]);
        }
        float s = 0.f;
#pragma unroll
        for (int k = 0; k < 16; k++) s += __expf(tmp[k] - mx);
        Cs[cb ^ 1][tid] = mx + __logf(s);
        cb ^= 1;
    }
    __syncthreads();
    Cmat[g * 256 + tid] = Cs[cb][tid];
}

// ---------------------------------------------------------------------------
// Serial combine over chunk boundaries. Block 0: forward (alpha at chunk
// starts). Block 1: backward (beta at chunk starts) + beta[T-1] = 0.
// 16 active lanes per block.
// ---------------------------------------------------------------------------
__global__ void combine_kernel(const float* __restrict__ Cmat,
                               const float* __restrict__ tr0,
                               const float* __restrict__ pis,
                               float* __restrict__ Va, float* __restrict__ Wb,
                               float* __restrict__ out_beta)
{
    const int lane = threadIdx.x;
    if (lane >= 16) return;
    const unsigned mask = 0xFFFFu;

    if (blockIdx.x == 0) {
        float v = tr0[lane] + pis[lane];   // a0
        Va[lane] = v;
        for (int gg = 0; gg < G_CHUNKS; gg++) {
            const float* Cg = Cmat + gg * 256;
            float tmp[16];
#pragma unroll
            for (int i = 0; i < 16; i++)
                tmp[i] = __shfl_sync(mask, v, i) + Cg[i * 16 + lane];
            float mx = tmp[0];
#pragma unroll
            for (int i = 1; i < 16; i++) mx = fmaxf(mx, tmp[i]);
            float s = 0.f;
#pragma unroll
            for (int i = 0; i < 16; i++) s += __expf(tmp[i] - mx);
            v = mx + __logf(s);
            Va[(gg + 1) * 16 + lane] = v;
        }
    } else {
        float w = 0.f;
        Wb[G_CHUNKS * 16 + lane] = 0.f;
        out_beta[(size_t)(T_LEN - 1) * 16 + lane] = 0.f;
        for (int gg = G_CHUNKS - 1; gg >= 0; gg--) {
            const float* Cg = Cmat + gg * 256 + lane * 16;
            float tmp[16];
#pragma unroll
            for (int j = 0; j < 16; j++)
                tmp[j] = __shfl_sync(mask, w, j) + Cg[j];
            float mx = tmp[0];
#pragma unroll
            for (int j = 1; j < 16; j++) mx = fmaxf(mx, tmp[j]);
            float s = 0.f;
#pragma unroll
            for (int j = 0; j < 16; j++) s += __expf(tmp[j] - mx);
            w = mx + __logf(s);
            Wb[gg * 16 + lane] = w;
        }
    }
}

// ---------------------------------------------------------------------------
// Scan pass 2: expand alpha (blocks [0, G)) and beta (blocks [G, 2G)) inside
// each chunk from boundary vectors. 16 active lanes per block.
// ---------------------------------------------------------------------------
__global__ void pass2_kernel(const float* __restrict__ trs,
                             const float* __restrict__ pis,
                             const float* __restrict__ Va,
                             const float* __restrict__ Wb,
                             float* __restrict__ out_alpha,
                             float* __restrict__ out_beta)
{
    const int lane = threadIdx.x;
    if (lane >= 16) return;
    const unsigned mask = 0xFFFFu;
    const int b = blockIdx.x;

    if (b < G_CHUNKS) {   // forward
        const int g  = b;
        const int t0 = g * CHUNK;
        const int t1 = min(t0 + CHUNK, NTRANS);
        float v = Va[g * 16 + lane];
        if (g == 0) out_alpha[lane] = v;
        for (int t = t0; t < t1; t++) {
            const float* M = trs + (size_t)t * 256;
            float tmp[16];
#pragma unroll
            for (int i = 0; i < 16; i++)
                tmp[i] = __shfl_sync(mask, v, i) + M[i * 16 + lane];
            float mx = tmp[0];
#pragma unroll
            for (int i = 1; i < 16; i++) mx = fmaxf(mx, tmp[i]);
            float s = 0.f;
#pragma unroll
            for (int i = 0; i < 16; i++) s += __expf(tmp[i] - mx);
            v = mx + __logf(s) + pis[(size_t)(t + 1) * 16 + lane];
            out_alpha[(size_t)(t + 1) * 16 + lane] = v;
        }
    } else {              // backward
        const int g  = b - G_CHUNKS;
        const int t0 = g * CHUNK;
        const int t1 = min(t0 + CHUNK, NTRANS);
        float w = Wb[(g + 1) * 16 + lane];
        for (int t = t1 - 1; t >= t0; t--) {
            const float* M = trs + (size_t)t * 256 + lane * 16;
            float u = w + pis[(size_t)(t + 1) * 16 + lane];
            float tmp[16];
#pragma unroll
            for (int j = 0; j < 16; j++)
                tmp[j] = __shfl_sync(mask, u, j) + M[j];
            float mx = tmp[0];
#pragma unroll
            for (int j = 1; j < 16; j++) mx = fmaxf(mx, tmp[j]);
            float s = 0.f;
#pragma unroll
            for (int j = 0; j < 16; j++) s += __expf(tmp[j] - mx);
            w = mx + __logf(s);
            out_beta[(size_t)t * 16 + lane] = w;
        }
    }
}

// ---------------------------------------------------------------------------
// Host launcher
// ---------------------------------------------------------------------------
extern "C" void kernel_launch(void* const* d_in, const int* in_sizes, int n_in,
                              void* d_out, int out_size)
{
    const float* s_arr = (const float*)d_in[0];
    const float* a_arr = (const float*)d_in[1];
    const float* pW1 = (const float*)d_in[2];  const float* pb1 = (const float*)d_in[3];
    const float* pW2 = (const float*)d_in[4];  const float* pb2 = (const float*)d_in[5];
    const float* pW3 = (const float*)d_in[6];  const float* pb3 = (const float*)d_in[7];
    const float* oW1 = (const float*)d_in[8];  const float* ob1 = (const float*)d_in[9];
    const float* oW2 = (const float*)d_in[10]; const float* ob2 = (const float*)d_in[11];
    const float* oW3 = (const float*)d_in[12]; const float* ob3 = (const float*)d_in[13];
    const float* als = (const float*)d_in[14];

    float* out = (float*)d_out;
    float* out_alpha = out + OFF_ALPHA;
    float* out_beta  = out + OFF_BETA;
    float* out_trs   = out + OFF_TRS;
    float* out_pis   = out + OFF_PIS;
    float* out_ent   = out + OFF_ENT;

    float *buf1, *buf2, *meanb, *logitsb, *Cmat, *Va, *Wb, *tr0;
    cudaGetSymbolAddress((void**)&buf1,   g_buf1);
    cudaGetSymbolAddress((void**)&buf2,   g_buf2);
    cudaGetSymbolAddress((void**)&meanb,  g_mean);
    cudaGetSymbolAddress((void**)&logitsb,g_logits);
    cudaGetSymbolAddress((void**)&Cmat,   g_Cmat);
    cudaGetSymbolAddress((void**)&Va,     g_Va);
    cudaGetSymbolAddress((void**)&Wb,     g_Wb);
    cudaGetSymbolAddress((void**)&tr0,    g_tr0);

    const int MB = T_LEN / 128;   // 512 row tiles

    // Policy MLP
    gemm_kernel<64,  256, true ><<<dim3(MB, 2), 256>>>(s_arr, pW1, pb1, buf1);
    gemm_kernel<256, 256, true ><<<dim3(MB, 2), 256>>>(buf1,  pW2, pb2, buf2);
    gemm_kernel<256, 128, false><<<dim3(MB, 1), 256>>>(buf2,  pW3, pb3, meanb);
    // Observation MLP
    gemm_kernel<64,  256, true ><<<dim3(MB, 2), 256>>>(s_arr, oW1, ob1, buf1);
    gemm_kernel<256, 256, true ><<<dim3(MB, 2), 256>>>(buf1,  oW2, ob2, buf2);
    gemm_kernel<256, 272, false><<<dim3(MB, 3), 256>>>(buf2,  oW3, ob3, logitsb);

    // Post-processing
    logpis_kernel<<<(T_LEN * DIM_C + 255) / 256, 256>>>(meanb, a_arr, als, out_pis);
    softmax_kernel<<<(T_LEN * 17 + 255) / 256, 256>>>(logitsb, out_trs, out_ent, tr0);

    // Parallel log-semiring scans
    pass1_kernel<<<G_CHUNKS, 256>>>(out_trs, out_pis, Cmat);
    combine_kernel<<<2, 32>>>(Cmat, tr0, out_pis, Va, Wb, out_beta);
    pass2_kernel<<<2 * G_CHUNKS, 32>>>(out_trs, out_pis, Va, Wb, out_alpha, out_beta);
}

// round 8
// speedup vs baseline: 1.2095x; 1.2095x over previous
#include <cuda_runtime.h>
#include <cfloat>
#include <math.h>
#include <stdint.h>

// ---------------------------------------------------------------------------
// Problem constants
// ---------------------------------------------------------------------------
#define T_LEN   65536
#define DIM_S   64
#define DIM_A   8
#define DIM_C   16
#define HDIM    256
#define NTRANS  (T_LEN - 1)          // 65535 transitions
#define CHUNK   256                  // transitions per scan chunk
#define G_CHUNKS 256                 // ceil(65535 / 256)
#define NGROUP  16                   // chunks per super-group
#define NSUPER  16                   // number of super-groups

// Output layout (floats), concatenated in reference return order:
// log_alpha [T,16], log_beta [T,16], log_trs [T-1,16,16], log_pis [T,16], entropy [T-1,16]
static const size_t OFF_ALPHA = 0;
static const size_t OFF_BETA  = (size_t)T_LEN * DIM_C;
static const size_t OFF_TRS   = 2ull * T_LEN * DIM_C;
static const size_t OFF_PIS   = OFF_TRS + (size_t)NTRANS * DIM_C * DIM_C;
static const size_t OFF_ENT   = OFF_PIS + (size_t)T_LEN * DIM_C;

// ---------------------------------------------------------------------------
// Device scratch (static __device__ arrays; no allocation APIs)
// ---------------------------------------------------------------------------
__device__ float g_h1p[(size_t)T_LEN * HDIM];             // policy hidden 1
__device__ float g_h1o[(size_t)T_LEN * HDIM];             // obs    hidden 1
__device__ float g_h2p[(size_t)T_LEN * HDIM];             // policy hidden 2
__device__ float g_h2o[(size_t)T_LEN * HDIM];             // obs    hidden 2
__device__ float g_mean[(size_t)T_LEN * (DIM_C * DIM_A)];
__device__ float g_logits[(size_t)T_LEN * ((DIM_C + 1) * DIM_C)];
__device__ float g_Cmat[G_CHUNKS * 256];                  // chunk transfer matrices
__device__ float g_P  [NSUPER * NGROUP * 256];            // group prefix products
__device__ float g_Suf[NSUPER * NGROUP * 256];            // group suffix products
__device__ float g_Vs[(NSUPER + 1) * 16];                 // alpha at super boundaries
__device__ float g_Wsv[(NSUPER + 1) * 16];                // beta  at super boundaries
__device__ float g_tr0[16];                               // log_trs_full[0, -1]

// ---------------------------------------------------------------------------
// SGEMM: C[T x N] = act(A[T x K] @ W[K x N] + b), fp32, 128x128x8 tiles,
// double-buffered shared memory, register-staged global loads.
// blockIdx.z selects between two independent (A, W, b, C) problem instances
// so both MLPs' layers run in a single launch.
// ---------------------------------------------------------------------------
template <int K, int N, bool RELU>
__global__ __launch_bounds__(256, 2) void gemm_kernel(
    const float* __restrict__ A0, const float* __restrict__ W0,
    const float* __restrict__ b0, float* __restrict__ C0,
    const float* __restrict__ A1, const float* __restrict__ W1,
    const float* __restrict__ b1, float* __restrict__ C1)
{
    constexpr int BM = 128, BN = 128, BK = 8;
    constexpr bool NG = (N % BN) != 0;   // needs column guards (N = 272)

    const float* __restrict__ A    = blockIdx.z ? A1 : A0;
    const float* __restrict__ W    = blockIdx.z ? W1 : W0;
    const float* __restrict__ bias = blockIdx.z ? b1 : b0;
    float*       __restrict__ C    = blockIdx.z ? C1 : C0;

    __shared__ float As[2][BK][BM + 4];
    __shared__ float Ws[2][BK][BN];

    const int tid  = threadIdx.x;
    const int row0 = blockIdx.x * BM;
    const int col0 = blockIdx.y * BN;
    const int tx   = tid & 15;    // 16 col groups of 8
    const int ty   = tid >> 4;    // 16 row groups of 8

    const int a_m = tid >> 1;           // 0..127
    const int a_k = (tid & 1) * 4;      // 0 or 4
    const int w_k = tid >> 5;           // 0..7
    const int w_n = (tid & 31) * 4;     // 0..124

    const float* Aptr = A + (size_t)(row0 + a_m) * K + a_k;
    const float* Wptr = W + (size_t)w_k * N + col0 + w_n;
    const int    wcn  = col0 + w_n;

    float acc[8][8];
#pragma unroll
    for (int i = 0; i < 8; i++)
#pragma unroll
        for (int j = 0; j < 8; j++) acc[i][j] = 0.f;

    auto loadW = [&](int k0) -> float4 {
        if (!NG) {
            return *reinterpret_cast<const float4*>(Wptr + (size_t)k0 * N);
        } else {
            const float* p = Wptr + (size_t)k0 * N;
            float4 wv;
            wv.x = (wcn + 0 < N) ? p[0] : 0.f;
            wv.y = (wcn + 1 < N) ? p[1] : 0.f;
            wv.z = (wcn + 2 < N) ? p[2] : 0.f;
            wv.w = (wcn + 3 < N) ? p[3] : 0.f;
            return wv;
        }
    };

    auto stage = [&](int st, float4 av, float4 wv) {
        As[st][a_k + 0][a_m] = av.x;
        As[st][a_k + 1][a_m] = av.y;
        As[st][a_k + 2][a_m] = av.z;
        As[st][a_k + 3][a_m] = av.w;
        *reinterpret_cast<float4*>(&Ws[st][w_k][w_n]) = wv;
    };

    auto compute = [&](int st) {
#pragma unroll
        for (int kk = 0; kk < BK; kk++) {
            float a[8], b[8];
            *reinterpret_cast<float4*>(&a[0]) =
                *reinterpret_cast<const float4*>(&As[st][kk][ty * 8]);
            *reinterpret_cast<float4*>(&a[4]) =
                *reinterpret_cast<const float4*>(&As[st][kk][ty * 8 + 4]);
            *reinterpret_cast<float4*>(&b[0]) =
                *reinterpret_cast<const float4*>(&Ws[st][kk][tx * 8]);
            *reinterpret_cast<float4*>(&b[4]) =
                *reinterpret_cast<const float4*>(&Ws[st][kk][tx * 8 + 4]);
#pragma unroll
            for (int i = 0; i < 8; i++)
#pragma unroll
                for (int j = 0; j < 8; j++)
                    acc[i][j] = fmaf(a[i], b[j], acc[i][j]);
        }
    };

    // Prologue: stage tile 0
    {
        float4 av = *reinterpret_cast<const float4*>(Aptr);
        float4 wv = loadW(0);
        stage(0, av, wv);
    }
    __syncthreads();

    int st = 0;
    for (int k0 = BK; k0 < K; k0 += BK) {
        float4 av = *reinterpret_cast<const float4*>(Aptr + k0);
        float4 wv = loadW(k0);
        compute(st);
        stage(st ^ 1, av, wv);
        __syncthreads();
        st ^= 1;
    }
    compute(st);

    float bb[8];
#pragma unroll
    for (int j = 0; j < 8; j++) {
        int cn = col0 + tx * 8 + j;
        bb[j] = (!NG || cn < N) ? bias[cn] : 0.f;
    }
#pragma unroll
    for (int i = 0; i < 8; i++) {
        const size_t r = (size_t)(row0 + ty * 8 + i);
#pragma unroll
        for (int j = 0; j < 8; j++) {
            int cn = col0 + tx * 8 + j;
            if (!NG || cn < N) {
                float v = acc[i][j] + bb[j];
                if (RELU) v = fmaxf(v, 0.f);
                C[r * N + cn] = v;
            }
        }
    }
}

// ---------------------------------------------------------------------------
// log_pis[t][c] = sum_a -0.5*((a - clip(mean))/std)^2 - logstd_a - 0.5*log(2pi)
// ---------------------------------------------------------------------------
__global__ void logpis_kernel(const float* __restrict__ mean,
                              const float* __restrict__ a_arr,
                              const float* __restrict__ a_log_std,
                              float* __restrict__ out_pis)
{
    __shared__ float s_inv_std[8];
    __shared__ float s_ls[8];
    if (threadIdx.x < 8) {
        float ls = tanhf(a_log_std[threadIdx.x]);
        ls = -5.0f + 3.5f * (ls + 1.0f);
        s_ls[threadIdx.x] = ls;
        s_inv_std[threadIdx.x] = expf(-ls);
    }
    __syncthreads();

    int idx = blockIdx.x * blockDim.x + threadIdx.x;
    if (idx >= T_LEN * DIM_C) return;

    float lsum = 0.f;
#pragma unroll
    for (int a = 0; a < 8; a++) lsum += s_ls[a];
    const float cst = -lsum - 4.0f * 1.8378770664093453f;  // 8 * 0.5*log(2pi)

    const int t = idx >> 4;
    const int c = idx & 15;
    const float* m  = mean + (size_t)t * 128 + c * 8;
    const float* av = a_arr + (size_t)t * 8;
    float s = 0.f;
#pragma unroll
    for (int a = 0; a < 8; a++) {
        float mm = fminf(fmaxf(m[a], -10.f), 10.f);
        float z = (av[a] - mm) * s_inv_std[a];
        s = fmaf(z, z, s);
    }
    out_pis[idx] = -0.5f * s + cst;
}

// ---------------------------------------------------------------------------
// log_softmax over groups of 16, plus entropy, plus log_tr0 extraction
// ---------------------------------------------------------------------------
__global__ void softmax_kernel(const float* __restrict__ logits,
                               float* __restrict__ out_trs,
                               float* __restrict__ out_ent,
                               float* __restrict__ tr0)
{
    int idx = blockIdx.x * blockDim.x + threadIdx.x;
    if (idx >= T_LEN * 17) return;
    const int t = idx / 17;
    const int g = idx - t * 17;
    const bool is0 = (t == 0 && g == 16);
    const bool isn = (t >= 1 && g < 16);
    if (!is0 && !isn) return;

    const float* row = logits + (size_t)t * 272 + g * 16;
    float v[16];
#pragma unroll
    for (int q = 0; q < 4; q++)
        *reinterpret_cast<float4*>(&v[q * 4]) =
            *reinterpret_cast<const float4*>(&row[q * 4]);

    float mx = v[0];
#pragma unroll
    for (int j = 1; j < 16; j++) mx = fmaxf(mx, v[j]);
    float s = 0.f, ws = 0.f;
#pragma unroll
    for (int j = 0; j < 16; j++) {
        float d = v[j] - mx;
        float e = __expf(d);
        s += e;
        ws = fmaf(d, e, ws);
    }
    const float ls  = __logf(s);
    const float lse = mx + ls;

    if (is0) {
#pragma unroll
        for (int j = 0; j < 16; j++) tr0[j] = v[j] - lse;
    } else {
        float* o = out_trs + (size_t)(t - 1) * 256 + g * 16;
#pragma unroll
        for (int j = 0; j < 16; j++) o[j] = v[j] - lse;
        // entropy = -(sum_j lt_j * exp(lt_j)) = ls - ws/s
        out_ent[(size_t)(t - 1) * 16 + g] = ls - ws / s;
    }
}

// ---------------------------------------------------------------------------
// Scan pass 1: per-chunk log-semiring transfer matrix
// C_g = M'_{t0} o M'_{t0+1} o ... ,  M'_t[i][j] = log_trs[t][i][j] + log_pis[t+1][j]
// One 256-thread CTA per chunk; thread (i,j) holds C[i][j].
// ---------------------------------------------------------------------------
__global__ __launch_bounds__(256) void pass1_kernel(
    const float* __restrict__ trs, const float* __restrict__ pis,
    float* __restrict__ Cmat)
{
    const int g   = blockIdx.x;
    const int tid = threadIdx.x;
    const int i   = tid >> 4;
    const int j   = tid & 15;
    const int t0  = g * CHUNK;
    const int t1  = min(t0 + CHUNK, NTRANS);

    __shared__ float Cs[2][256];
    __shared__ float Ms[256];

    Cs[0][tid] = trs[(size_t)t0 * 256 + tid] + pis[(size_t)(t0 + 1) * 16 + j];
    int cb = 0;

    for (int t = t0 + 1; t < t1; t++) {
        float mv = trs[(size_t)t * 256 + tid] + pis[(size_t)(t + 1) * 16 + j];
        __syncthreads();          // prior Ms reads done, Cs[cb] visible
        Ms[tid] = mv;
        __syncthreads();

        float tmp[16];
        float mx = -FLT_MAX;
#pragma unroll
        for (int k = 0; k < 16; k++) {
            tmp[k] = Cs[cb][i * 16 + k] + Ms[k * 16 + j];
            mx = fmaxf(mx, tmp[k]);
        }
        float s = 0.f;
#pragma unroll
        for (int k = 0; k < 16; k++) s += __expf(tmp[k] - mx);
        Cs[cb ^ 1][tid] = mx + __logf(s);
        cb ^= 1;
    }
    __syncthreads();
    Cmat[g * 256 + tid] = Cs[cb][tid];
}

// ---------------------------------------------------------------------------
// Group prefix/suffix products over 16-chunk super-groups.
// Block b < 16  : prefixes  P[s][r] = C_{16s} o ... o C_{16s+r}     (r=0..15)
// Block b >= 16 : suffixes  Suf[s][r] = C_{16s+r} o ... o C_{16s+15}
// P[s][15] is the super-group matrix S_s.
// ---------------------------------------------------------------------------
__global__ __launch_bounds__(256) void superprod_kernel(
    const float* __restrict__ Cmat, float* __restrict__ P, float* __restrict__ Suf)
{
    const int s   = blockIdx.x & 15;
    const int dir = blockIdx.x >> 4;
    const int tid = threadIdx.x;
    const int i   = tid >> 4;
    const int j   = tid & 15;

    __shared__ float Cs[2][256];
    __shared__ float Ms[256];
    int cb = 0;

    if (dir == 0) {
        Cs[0][tid] = Cmat[(s * 16) * 256 + tid];
        P[(s * 16) * 256 + tid] = Cs[0][tid];
        for (int r = 1; r < 16; r++) {
            float mv = Cmat[(s * 16 + r) * 256 + tid];
            __syncthreads();
            Ms[tid] = mv;
            __syncthreads();
            float tmp[16];
            float mx = -FLT_MAX;
#pragma unroll
            for (int k = 0; k < 16; k++) {
                tmp[k] = Cs[cb][i * 16 + k] + Ms[k * 16 + j];
                mx = fmaxf(mx, tmp[k]);
            }
            float ssum = 0.f;
#pragma unroll
            for (int k = 0; k < 16; k++) ssum += __expf(tmp[k] - mx);
            float res = mx + __logf(ssum);
            Cs[cb ^ 1][tid] = res;
            P[(s * 16 + r) * 256 + tid] = res;
            cb ^= 1;
        }
    } else {
        Cs[0][tid] = Cmat[(s * 16 + 15) * 256 + tid];
        Suf[(s * 16 + 15) * 256 + tid] = Cs[0][tid];
        for (int r = 14; r >= 0; r--) {
            float mv = Cmat[(s * 16 + r) * 256 + tid];
            __syncthreads();
            Ms[tid] = mv;
            __syncthreads();
            // new = C_r o cur : new[i][j] = LSE_k(C_r[i][k] + cur[k][j])
            float tmp[16];
            float mx = -FLT_MAX;
#pragma unroll
            for (int k = 0; k < 16; k++) {
                tmp[k] = Ms[i * 16 + k] + Cs[cb][k * 16 + j];
                mx = fmaxf(mx, tmp[k]);
            }
            float ssum = 0.f;
#pragma unroll
            for (int k = 0; k < 16; k++) ssum += __expf(tmp[k] - mx);
            float res = mx + __logf(ssum);
            Cs[cb ^ 1][tid] = res;
            Suf[(s * 16 + r) * 256 + tid] = res;
            cb ^= 1;
        }
    }
}

// ---------------------------------------------------------------------------
// Serial combine over SUPER-group boundaries (16 steps each direction).
// Block 0: forward Vs[0..16]. Block 1: backward Ws[16..0] + beta[T-1] = 0.
// ---------------------------------------------------------------------------
__global__ void combine2_kernel(const float* __restrict__ P,
                                const float* __restrict__ tr0,
                                const float* __restrict__ pis,
                                float* __restrict__ Vs, float* __restrict__ Wsv,
                                float* __restrict__ out_beta)
{
    const int lane = threadIdx.x;
    if (lane >= 16) return;
    const unsigned mask = 0xFFFFu;

    if (blockIdx.x == 0) {
        float v = tr0[lane] + pis[lane];   // a0
        Vs[lane] = v;
        for (int s = 0; s < NSUPER; s++) {
            const float* S = P + (s * 16 + 15) * 256;   // S_s
            float tmp[16];
#pragma unroll
            for (int i = 0; i < 16; i++)
                tmp[i] = __shfl_sync(mask, v, i) + S[i * 16 + lane];
            float mx = tmp[0];
#pragma unroll
            for (int i = 1; i < 16; i++) mx = fmaxf(mx, tmp[i]);
            float ssum = 0.f;
#pragma unroll
            for (int i = 0; i < 16; i++) ssum += __expf(tmp[i] - mx);
            v = mx + __logf(ssum);
            Vs[(s + 1) * 16 + lane] = v;
        }
    } else {
        float w = 0.f;
        Wsv[NSUPER * 16 + lane] = 0.f;
        out_beta[(size_t)(T_LEN - 1) * 16 + lane] = 0.f;
        for (int s = NSUPER - 1; s >= 0; s--) {
            const float* S = P + (s * 16 + 15) * 256 + lane * 16;  // row `lane` of S_s
            float tmp[16];
#pragma unroll
            for (int j = 0; j < 16; j++)
                tmp[j] = __shfl_sync(mask, w, j) + S[j];
            float mx = tmp[0];
#pragma unroll
            for (int j = 1; j < 16; j++) mx = fmaxf(mx, tmp[j]);
            float ssum = 0.f;
#pragma unroll
            for (int j = 0; j < 16; j++) ssum += __expf(tmp[j] - mx);
            w = mx + __logf(ssum);
            Wsv[s * 16 + lane] = w;
        }
    }
}

// ---------------------------------------------------------------------------
// Scan pass 2: expand alpha (blocks [0, G)) and beta (blocks [G, 2G)) inside
// each chunk. Chunk boundary vectors reconstructed from super boundaries +
// group prefix/suffix products (one extra LSE matvec at chunk start).
// ---------------------------------------------------------------------------
__global__ void pass2_kernel(const float* __restrict__ trs,
                             const float* __restrict__ pis,
                             const float* __restrict__ P,
                             const float* __restrict__ Suf,
                             const float* __restrict__ Vs,
                             const float* __restrict__ Wsv,
                             float* __restrict__ out_alpha,
                             float* __restrict__ out_beta)
{
    const int lane = threadIdx.x;
    if (lane >= 16) return;
    const unsigned mask = 0xFFFFu;
    const int b = blockIdx.x;

    if (b < G_CHUNKS) {   // forward
        const int g  = b;
        const int s  = g >> 4;
        const int r  = g & 15;
        const int t0 = g * CHUNK;
        const int t1 = min(t0 + CHUNK, NTRANS);

        float v;
        {
            float vs = Vs[s * 16 + lane];
            if (r == 0) {
                v = vs;
            } else {
                // v = Vs[s] (x) P[s][r-1]
                const float* Pm = P + (s * 16 + (r - 1)) * 256;
                float tmp[16];
#pragma unroll
                for (int i = 0; i < 16; i++)
                    tmp[i] = __shfl_sync(mask, vs, i) + Pm[i * 16 + lane];
                float mx = tmp[0];
#pragma unroll
                for (int i = 1; i < 16; i++) mx = fmaxf(mx, tmp[i]);
                float ssum = 0.f;
#pragma unroll
                for (int i = 0; i < 16; i++) ssum += __expf(tmp[i] - mx);
                v = mx + __logf(ssum);
            }
        }
        if (g == 0) out_alpha[lane] = v;

        for (int t = t0; t < t1; t++) {
            const float* M = trs + (size_t)t * 256;
            float tmp[16];
#pragma unroll
            for (int i = 0; i < 16; i++)
                tmp[i] = __shfl_sync(mask, v, i) + M[i * 16 + lane];
            float mx = tmp[0];
#pragma unroll
            for (int i = 1; i < 16; i++) mx = fmaxf(mx, tmp[i]);
            float ssum = 0.f;
#pragma unroll
            for (int i = 0; i < 16; i++) ssum += __expf(tmp[i] - mx);
            v = mx + __logf(ssum) + pis[(size_t)(t + 1) * 16 + lane];
            out_alpha[(size_t)(t + 1) * 16 + lane] = v;
        }
    } else {              // backward
        const int g  = b - G_CHUNKS;
        const int s  = g >> 4;
        const int r  = g & 15;
        const int t0 = g * CHUNK;
        const int t1 = min(t0 + CHUNK, NTRANS);

        float w;
        {
            float wsv = Wsv[(s + 1) * 16 + lane];
            if (r == 15) {
                w = wsv;
            } else {
                // w = Suf[s][r+1] (x) Ws[s+1]   (row = lane)
                const float* Sf = Suf + (s * 16 + (r + 1)) * 256 + lane * 16;
                float tmp[16];
#pragma unroll
                for (int j = 0; j < 16; j++)
                    tmp[j] = Sf[j] + __shfl_sync(mask, wsv, j);
                float mx = tmp[0];
#pragma unroll
                for (int j = 1; j < 16; j++) mx = fmaxf(mx, tmp[j]);
                float ssum = 0.f;
#pragma unroll
                for (int j = 0; j < 16; j++) ssum += __expf(tmp[j] - mx);
                w = mx + __logf(ssum);
            }
        }

        for (int t = t1 - 1; t >= t0; t--) {
            const float* M = trs + (size_t)t * 256 + lane * 16;
            float u = w + pis[(size_t)(t + 1) * 16 + lane];
            float tmp[16];
#pragma unroll
            for (int j = 0; j < 16; j++)
                tmp[j] = __shfl_sync(mask, u, j) + M[j];
            float mx = tmp[0];
#pragma unroll
            for (int j = 1; j < 16; j++) mx = fmaxf(mx, tmp[j]);
            float ssum = 0.f;
#pragma unroll
            for (int j = 0; j < 16; j++) ssum += __expf(tmp[j] - mx);
            w = mx + __logf(ssum);
            out_beta[(size_t)t * 16 + lane] = w;
        }
    }
}

// ---------------------------------------------------------------------------
// Host launcher
// ---------------------------------------------------------------------------
extern "C" void kernel_launch(void* const* d_in, const int* in_sizes, int n_in,
                              void* d_out, int out_size)
{
    const float* s_arr = (const float*)d_in[0];
    const float* a_arr = (const float*)d_in[1];
    const float* pW1 = (const float*)d_in[2];  const float* pb1 = (const float*)d_in[3];
    const float* pW2 = (const float*)d_in[4];  const float* pb2 = (const float*)d_in[5];
    const float* pW3 = (const float*)d_in[6];  const float* pb3 = (const float*)d_in[7];
    const float* oW1 = (const float*)d_in[8];  const float* ob1 = (const float*)d_in[9];
    const float* oW2 = (const float*)d_in[10]; const float* ob2 = (const float*)d_in[11];
    const float* oW3 = (const float*)d_in[12]; const float* ob3 = (const float*)d_in[13];
    const float* als = (const float*)d_in[14];

    float* out = (float*)d_out;
    float* out_alpha = out + OFF_ALPHA;
    float* out_beta  = out + OFF_BETA;
    float* out_trs   = out + OFF_TRS;
    float* out_pis   = out + OFF_PIS;
    float* out_ent   = out + OFF_ENT;

    float *h1p, *h1o, *h2p, *h2o, *meanb, *logitsb, *Cmat, *Pm, *Sf, *Vs, *Wsv, *tr0;
    cudaGetSymbolAddress((void**)&h1p,    g_h1p);
    cudaGetSymbolAddress((void**)&h1o,    g_h1o);
    cudaGetSymbolAddress((void**)&h2p,    g_h2p);
    cudaGetSymbolAddress((void**)&h2o,    g_h2o);
    cudaGetSymbolAddress((void**)&meanb,  g_mean);
    cudaGetSymbolAddress((void**)&logitsb,g_logits);
    cudaGetSymbolAddress((void**)&Cmat,   g_Cmat);
    cudaGetSymbolAddress((void**)&Pm,     g_P);
    cudaGetSymbolAddress((void**)&Sf,     g_Suf);
    cudaGetSymbolAddress((void**)&Vs,     g_Vs);
    cudaGetSymbolAddress((void**)&Wsv,    g_Wsv);
    cudaGetSymbolAddress((void**)&tr0,    g_tr0);

    const int MB = T_LEN / 128;   // 512 row tiles

    // Layer 1 (both MLPs fused via blockIdx.z)
    gemm_kernel<64, 256, true ><<<dim3(MB, 2, 2), 256>>>(
        s_arr, pW1, pb1, h1p,  s_arr, oW1, ob1, h1o);
    // Layer 2 (both MLPs fused)
    gemm_kernel<256, 256, true ><<<dim3(MB, 2, 2), 256>>>(
        h1p, pW2, pb2, h2p,  h1o, oW2, ob2, h2o);
    // Layer 3 (different N -> separate launches)
    gemm_kernel<256, 128, false><<<dim3(MB, 1, 1), 256>>>(
        h2p, pW3, pb3, meanb,  h2p, pW3, pb3, meanb);
    gemm_kernel<256, 272, false><<<dim3(MB, 3, 1), 256>>>(
        h2o, oW3, ob3, logitsb,  h2o, oW3, ob3, logitsb);

    // Post-processing
    logpis_kernel<<<(T_LEN * DIM_C + 255) / 256, 256>>>(meanb, a_arr, als, out_pis);
    softmax_kernel<<<(T_LEN * 17 + 255) / 256, 256>>>(logitsb, out_trs, out_ent, tr0);

    // Parallel log-semiring scans
    pass1_kernel<<<G_CHUNKS, 256>>>(out_trs, out_pis, Cmat);
    superprod_kernel<<<2 * NSUPER, 256>>>(Cmat, Pm, Sf);
    combine2_kernel<<<2, 32>>>(Pm, tr0, out_pis, Vs, Wsv, out_beta);
    pass2_kernel<<<2 * G_CHUNKS, 32>>>(out_trs, out_pis, Pm, Sf, Vs, Wsv,
                                       out_alpha, out_beta);
}

// round 9
// speedup vs baseline: 1.8535x; 1.5324x over previous
#include <cuda_runtime.h>
#include <cuda_bf16.h>
#include <cfloat>
#include <math.h>
#include <stdint.h>

// ---------------------------------------------------------------------------
// Problem constants
// ---------------------------------------------------------------------------
#define T_LEN   65536
#define DIM_S   64
#define DIM_A   8
#define DIM_C   16
#define HDIM    256
#define NTRANS  (T_LEN - 1)          // 65535 transitions
#define CHUNK   256                  // transitions per scan chunk
#define G_CHUNKS 256                 // ceil(65535 / 256)
#define NGROUP  16                   // chunks per super-group
#define NSUPER  16                   // number of super-groups

// Output layout (floats), concatenated in reference return order:
// log_alpha [T,16], log_beta [T,16], log_trs [T-1,16,16], log_pis [T,16], entropy [T-1,16]
static const size_t OFF_ALPHA = 0;
static const size_t OFF_BETA  = (size_t)T_LEN * DIM_C;
static const size_t OFF_TRS   = 2ull * T_LEN * DIM_C;
static const size_t OFF_PIS   = OFF_TRS + (size_t)NTRANS * DIM_C * DIM_C;
static const size_t OFF_ENT   = OFF_PIS + (size_t)T_LEN * DIM_C;

// ---------------------------------------------------------------------------
// Device scratch (static __device__ arrays; no allocation APIs)
// ---------------------------------------------------------------------------
__device__ float g_h1p[(size_t)T_LEN * HDIM];
__device__ float g_h1o[(size_t)T_LEN * HDIM];
__device__ float g_h2p[(size_t)T_LEN * HDIM];
__device__ float g_h2o[(size_t)T_LEN * HDIM];
__device__ float g_mean[(size_t)T_LEN * (DIM_C * DIM_A)];
__device__ float g_logits[(size_t)T_LEN * ((DIM_C + 1) * DIM_C)];
__device__ float g_Cmat[G_CHUNKS * 256];
__device__ float g_P  [NSUPER * NGROUP * 256];
__device__ float g_Suf[NSUPER * NGROUP * 256];
__device__ float g_Vs[(NSUPER + 1) * 16];
__device__ float g_Wsv[(NSUPER + 1) * 16];
__device__ float g_tr0[16];

// ---------------------------------------------------------------------------
// Split-bf16 helpers
// ---------------------------------------------------------------------------
__device__ __forceinline__ uint32_t pack2(__nv_bfloat16 a, __nv_bfloat16 b) {
    return (uint32_t)__bfloat16_as_ushort(a) |
           ((uint32_t)__bfloat16_as_ushort(b) << 16);
}
// Split (x, y) into hi/lo bf16 pairs packed as (low-half = first element).
__device__ __forceinline__ void split_pair(float x, float y,
                                           uint32_t& hi, uint32_t& lo) {
    __nv_bfloat16 xh = __float2bfloat16(x);
    __nv_bfloat16 yh = __float2bfloat16(y);
    float xr = x - __bfloat162float(xh);
    float yr = y - __bfloat162float(yh);
    hi = pack2(xh, yh);
    lo = pack2(__float2bfloat16(xr), __float2bfloat16(yr));
}

__device__ __forceinline__ void mma16816(float c[4], const uint32_t a[4],
                                         const uint32_t b[2]) {
    asm volatile(
        "mma.sync.aligned.m16n8k16.row.col.f32.bf16.bf16.f32 "
        "{%0,%1,%2,%3}, {%4,%5,%6,%7}, {%8,%9}, {%0,%1,%2,%3};\n"
        : "+f"(c[0]), "+f"(c[1]), "+f"(c[2]), "+f"(c[3])
        : "r"(a[0]), "r"(a[1]), "r"(a[2]), "r"(a[3]), "r"(b[0]), "r"(b[1]));
}

// ---------------------------------------------------------------------------
// Tensor-core GEMM: C[M x N] = act(A[M x K] @ W[K x N] + b), fp32 in/out,
// split-bf16 x3 mma (hi*hi + hi*lo + lo*hi), fp32 accumulate.
// 128x128x16 CTA tile, 8 warps (2x4), 64x32 warp tile, double-buffered smem.
// blockIdx.z selects between two independent problem instances.
// ---------------------------------------------------------------------------
#define BKW 9   // 32-bit words per smem row (8 data + 1 pad)

template <int K, int N, bool RELU>
__global__ __launch_bounds__(256, 2) void gemm_tc(
    const float* __restrict__ A0, const float* __restrict__ W0,
    const float* __restrict__ b0, float* __restrict__ C0,
    const float* __restrict__ A1, const float* __restrict__ W1,
    const float* __restrict__ b1, float* __restrict__ C1)
{
    constexpr int BM = 128, BN = 128, BK = 16;
    constexpr int NSLAB = K / BK;
    constexpr bool NG = (N % BN) != 0;   // N = 272 tail guards

    const float* __restrict__ A    = blockIdx.z ? A1 : A0;
    const float* __restrict__ W    = blockIdx.z ? W1 : W0;
    const float* __restrict__ bias = blockIdx.z ? b1 : b0;
    float*       __restrict__ C    = blockIdx.z ? C1 : C0;

    // smem planes per stage: [A_hi | A_lo | W_hi | W_lo], each BM*BKW words.
    constexpr int PL = BM * BKW;        // 1152 words
    __shared__ uint32_t sm[2][4 * PL];  // 36864 bytes total

    const int tid   = threadIdx.x;
    const int lane  = tid & 31;
    const int warp  = tid >> 5;
    const int warpM = (warp & 1) * 64;  // 2 warp rows
    const int warpN = (warp >> 1) * 32; // 4 warp cols
    const int g = lane >> 2;            // 0..7
    const int c = lane & 3;             // 0..3

    const int row0 = blockIdx.x * BM;
    const int col0 = blockIdx.y * BN;

    // Staging assignments
    const int am = tid >> 1;            // 0..127  (A row within tile)
    const int ak = (tid & 1) * 8;       // k offset 0 or 8
    const int wn = tid & 127;           // 0..127  (W col within tile)
    const int wk = (tid >> 7) * 8;      // k offset 0 or 8
    const int gcol = col0 + wn;
    const bool wvalid = (!NG) || (gcol < N);

    const float* Aptr = A + (size_t)(row0 + am) * K + ak;
    const float* Wptr = W + gcol;

    float acc[4][4][4];
#pragma unroll
    for (int mt = 0; mt < 4; mt++)
#pragma unroll
        for (int nt = 0; nt < 4; nt++)
#pragma unroll
            for (int q = 0; q < 4; q++) acc[mt][nt][q] = 0.f;

    float4 va0, va1;
    float  wv[8];

    auto prefetch = [&](int k0) {
        va0 = *reinterpret_cast<const float4*>(Aptr + k0);
        va1 = *reinterpret_cast<const float4*>(Aptr + k0 + 4);
#pragma unroll
        for (int i = 0; i < 8; i++)
            wv[i] = wvalid ? Wptr[(size_t)(k0 + wk + i) * N] : 0.f;
    };

    auto stage = [&](int st) {
        uint32_t* AH = &sm[st][0];
        uint32_t* AL = &sm[st][PL];
        uint32_t* WH = &sm[st][2 * PL];
        uint32_t* WL = &sm[st][3 * PL];
        uint32_t hi, lo;
        const int abase = am * BKW + (ak >> 1);
        split_pair(va0.x, va0.y, hi, lo); AH[abase + 0] = hi; AL[abase + 0] = lo;
        split_pair(va0.z, va0.w, hi, lo); AH[abase + 1] = hi; AL[abase + 1] = lo;
        split_pair(va1.x, va1.y, hi, lo); AH[abase + 2] = hi; AL[abase + 2] = lo;
        split_pair(va1.z, va1.w, hi, lo); AH[abase + 3] = hi; AL[abase + 3] = lo;
        const int wbase = wn * BKW + (wk >> 1);
#pragma unroll
        for (int j = 0; j < 4; j++) {
            split_pair(wv[2 * j], wv[2 * j + 1], hi, lo);
            WH[wbase + j] = hi; WL[wbase + j] = lo;
        }
    };

    auto compute = [&](int st) {
        const uint32_t* AH = &sm[st][0];
        const uint32_t* AL = &sm[st][PL];
        const uint32_t* WH = &sm[st][2 * PL];
        const uint32_t* WL = &sm[st][3 * PL];

        uint32_t bh[4][2], bl[4][2];
#pragma unroll
        for (int nt = 0; nt < 4; nt++) {
            const int nb = (warpN + nt * 8 + g) * BKW + c;
            bh[nt][0] = WH[nb];     bh[nt][1] = WH[nb + 4];
            bl[nt][0] = WL[nb];     bl[nt][1] = WL[nb + 4];
        }
#pragma unroll
        for (int mt = 0; mt < 4; mt++) {
            const int r0 = (warpM + mt * 16 + g) * BKW + c;
            const int r1 = r0 + 8 * BKW;
            uint32_t ah[4], al[4];
            ah[0] = AH[r0];     ah[1] = AH[r1];
            ah[2] = AH[r0 + 4]; ah[3] = AH[r1 + 4];
            al[0] = AL[r0];     al[1] = AL[r1];
            al[2] = AL[r0 + 4]; al[3] = AL[r1 + 4];
#pragma unroll
            for (int nt = 0; nt < 4; nt++) {
                mma16816(acc[mt][nt], ah, bh[nt]);
                mma16816(acc[mt][nt], ah, bl[nt]);
                mma16816(acc[mt][nt], al, bh[nt]);
            }
        }
    };

    // Pipeline
    prefetch(0);
    stage(0);
    __syncthreads();
    int st = 0;
#pragma unroll 1
    for (int s = 1; s < NSLAB; s++) {
        prefetch(s * BK);
        compute(st);
        stage(st ^ 1);
        __syncthreads();
        st ^= 1;
    }
    compute(st);

    // Epilogue
#pragma unroll
    for (int mt = 0; mt < 4; mt++) {
#pragma unroll
        for (int nt = 0; nt < 4; nt++) {
            const int col = col0 + warpN + nt * 8 + c * 2;
            if (NG && col >= N) continue;
            const float bx = bias[col];
            const float by = bias[col + 1];
            const int rowA = row0 + warpM + mt * 16 + g;
            float v0 = acc[mt][nt][0] + bx;
            float v1 = acc[mt][nt][1] + by;
            float v2 = acc[mt][nt][2] + bx;
            float v3 = acc[mt][nt][3] + by;
            if (RELU) {
                v0 = fmaxf(v0, 0.f); v1 = fmaxf(v1, 0.f);
                v2 = fmaxf(v2, 0.f); v3 = fmaxf(v3, 0.f);
            }
            *reinterpret_cast<float2*>(&C[(size_t)rowA * N + col]) =
                make_float2(v0, v1);
            *reinterpret_cast<float2*>(&C[(size_t)(rowA + 8) * N + col]) =
                make_float2(v2, v3);
        }
    }
}

// ---------------------------------------------------------------------------
// log_pis[t][c] = sum_a -0.5*((a - clip(mean))/std)^2 - logstd_a - 0.5*log(2pi)
// ---------------------------------------------------------------------------
__global__ void logpis_kernel(const float* __restrict__ mean,
                              const float* __restrict__ a_arr,
                              const float* __restrict__ a_log_std,
                              float* __restrict__ out_pis)
{
    __shared__ float s_inv_std[8];
    __shared__ float s_ls[8];
    if (threadIdx.x < 8) {
        float ls = tanhf(a_log_std[threadIdx.x]);
        ls = -5.0f + 3.5f * (ls + 1.0f);
        s_ls[threadIdx.x] = ls;
        s_inv_std[threadIdx.x] = expf(-ls);
    }
    __syncthreads();

    int idx = blockIdx.x * blockDim.x + threadIdx.x;
    if (idx >= T_LEN * DIM_C) return;

    float lsum = 0.f;
#pragma unroll
    for (int a = 0; a < 8; a++) lsum += s_ls[a];
    const float cst = -lsum - 4.0f * 1.8378770664093453f;

    const int t = idx >> 4;
    const int c = idx & 15;
    const float* m  = mean + (size_t)t * 128 + c * 8;
    const float* av = a_arr + (size_t)t * 8;
    float s = 0.f;
#pragma unroll
    for (int a = 0; a < 8; a++) {
        float mm = fminf(fmaxf(m[a], -10.f), 10.f);
        float z = (av[a] - mm) * s_inv_std[a];
        s = fmaf(z, z, s);
    }
    out_pis[idx] = -0.5f * s + cst;
}

// ---------------------------------------------------------------------------
// log_softmax over groups of 16, plus entropy, plus log_tr0 extraction
// ---------------------------------------------------------------------------
__global__ void softmax_kernel(const float* __restrict__ logits,
                               float* __restrict__ out_trs,
                               float* __restrict__ out_ent,
                               float* __restrict__ tr0)
{
    int idx = blockIdx.x * blockDim.x + threadIdx.x;
    if (idx >= T_LEN * 17) return;
    const int t = idx / 17;
    const int g = idx - t * 17;
    const bool is0 = (t == 0 && g == 16);
    const bool isn = (t >= 1 && g < 16);
    if (!is0 && !isn) return;

    const float* row = logits + (size_t)t * 272 + g * 16;
    float v[16];
#pragma unroll
    for (int q = 0; q < 4; q++)
        *reinterpret_cast<float4*>(&v[q * 4]) =
            *reinterpret_cast<const float4*>(&row[q * 4]);

    float mx = v[0];
#pragma unroll
    for (int j = 1; j < 16; j++) mx = fmaxf(mx, v[j]);
    float s = 0.f, ws = 0.f;
#pragma unroll
    for (int j = 0; j < 16; j++) {
        float d = v[j] - mx;
        float e = __expf(d);
        s += e;
        ws = fmaf(d, e, ws);
    }
    const float ls  = __logf(s);
    const float lse = mx + ls;

    if (is0) {
#pragma unroll
        for (int j = 0; j < 16; j++) tr0[j] = v[j] - lse;
    } else {
        float* o = out_trs + (size_t)(t - 1) * 256 + g * 16;
#pragma unroll
        for (int j = 0; j < 16; j++) o[j] = v[j] - lse;
        out_ent[(size_t)(t - 1) * 16 + g] = ls - ws / s;
    }
}

// ---------------------------------------------------------------------------
// Scan pass 1: per-chunk log-semiring transfer matrix
// ---------------------------------------------------------------------------
__global__ __launch_bounds__(256) void pass1_kernel(
    const float* __restrict__ trs, const float* __restrict__ pis,
    float* __restrict__ Cmat)
{
    const int g   = blockIdx.x;
    const int tid = threadIdx.x;
    const int i   = tid >> 4;
    const int j   = tid & 15;
    const int t0  = g * CHUNK;
    const int t1  = min(t0 + CHUNK, NTRANS);

    __shared__ float Cs[2][256];
    __shared__ float Ms[256];

    Cs[0][tid] = trs[(size_t)t0 * 256 + tid] + pis[(size_t)(t0 + 1) * 16 + j];
    int cb = 0;

    for (int t = t0 + 1; t < t1; t++) {
        float mv = trs[(size_t)t * 256 + tid] + pis[(size_t)(t + 1) * 16 + j];
        __syncthreads();
        Ms[tid] = mv;
        __syncthreads();

        float tmp[16];
        float mx = -FLT_MAX;
#pragma unroll
        for (int k = 0; k < 16; k++) {
            tmp[k] = Cs[cb][i * 16 + k] + Ms[k * 16 + j];
            mx = fmaxf(mx, tmp[k]);
        }
        float s = 0.f;
#pragma unroll
        for (int k = 0; k < 16; k++) s += __expf(tmp[k] - mx);
        Cs[cb ^ 1][tid] = mx + __logf(s);
        cb ^= 1;
    }
    __syncthreads();
    Cmat[g * 256 + tid] = Cs[cb][tid];
}

// ---------------------------------------------------------------------------
// Group prefix/suffix products over 16-chunk super-groups.
// ---------------------------------------------------------------------------
__global__ __launch_bounds__(256) void superprod_kernel(
    const float* __restrict__ Cmat, float* __restrict__ P, float* __restrict__ Suf)
{
    const int s   = blockIdx.x & 15;
    const int dir = blockIdx.x >> 4;
    const int tid = threadIdx.x;
    const int i   = tid >> 4;
    const int j   = tid & 15;

    __shared__ float Cs[2][256];
    __shared__ float Ms[256];
    int cb = 0;

    if (dir == 0) {
        Cs[0][tid] = Cmat[(s * 16) * 256 + tid];
        P[(s * 16) * 256 + tid] = Cs[0][tid];
        for (int r = 1; r < 16; r++) {
            float mv = Cmat[(s * 16 + r) * 256 + tid];
            __syncthreads();
            Ms[tid] = mv;
            __syncthreads();
            float tmp[16];
            float mx = -FLT_MAX;
#pragma unroll
            for (int k = 0; k < 16; k++) {
                tmp[k] = Cs[cb][i * 16 + k] + Ms[k * 16 + j];
                mx = fmaxf(mx, tmp[k]);
            }
            float ssum = 0.f;
#pragma unroll
            for (int k = 0; k < 16; k++) ssum += __expf(tmp[k] - mx);
            float res = mx + __logf(ssum);
            Cs[cb ^ 1][tid] = res;
            P[(s * 16 + r) * 256 + tid] = res;
            cb ^= 1;
        }
    } else {
        Cs[0][tid] = Cmat[(s * 16 + 15) * 256 + tid];
        Suf[(s * 16 + 15) * 256 + tid] = Cs[0][tid];
        for (int r = 14; r >= 0; r--) {
            float mv = Cmat[(s * 16 + r) * 256 + tid];
            __syncthreads();
            Ms[tid] = mv;
            __syncthreads();
            float tmp[16];
            float mx = -FLT_MAX;
#pragma unroll
            for (int k = 0; k < 16; k++) {
                tmp[k] = Ms[i * 16 + k] + Cs[cb][k * 16 + j];
                mx = fmaxf(mx, tmp[k]);
            }
            float ssum = 0.f;
#pragma unroll
            for (int k = 0; k < 16; k++) ssum += __expf(tmp[k] - mx);
            float res = mx + __logf(ssum);
            Cs[cb ^ 1][tid] = res;
            Suf[(s * 16 + r) * 256 + tid] = res;
            cb ^= 1;
        }
    }
}

// ---------------------------------------------------------------------------
// Serial combine over SUPER-group boundaries (16 steps each direction).
// ---------------------------------------------------------------------------
__global__ void combine2_kernel(const float* __restrict__ P,
                                const float* __restrict__ tr0,
                                const float* __restrict__ pis,
                                float* __restrict__ Vs, float* __restrict__ Wsv,
                                float* __restrict__ out_beta)
{
    const int lane = threadIdx.x;
    if (lane >= 16) return;
    const unsigned mask = 0xFFFFu;

    if (blockIdx.x == 0) {
        float v = tr0[lane] + pis[lane];   // a0
        Vs[lane] = v;
        for (int s = 0; s < NSUPER; s++) {
            const float* S = P + (s * 16 + 15) * 256;
            float tmp[16];
#pragma unroll
            for (int i = 0; i < 16; i++)
                tmp[i] = __shfl_sync(mask, v, i) + S[i * 16 + lane];
            float mx = tmp[0];
#pragma unroll
            for (int i = 1; i < 16; i++) mx = fmaxf(mx, tmp[i]);
            float ssum = 0.f;
#pragma unroll
            for (int i = 0; i < 16; i++) ssum += __expf(tmp[i] - mx);
            v = mx + __logf(ssum);
            Vs[(s + 1) * 16 + lane] = v;
        }
    } else {
        float w = 0.f;
        Wsv[NSUPER * 16 + lane] = 0.f;
        out_beta[(size_t)(T_LEN - 1) * 16 + lane] = 0.f;
        for (int s = NSUPER - 1; s >= 0; s--) {
            const float* S = P + (s * 16 + 15) * 256 + lane * 16;
            float tmp[16];
#pragma unroll
            for (int j = 0; j < 16; j++)
                tmp[j] = __shfl_sync(mask, w, j) + S[j];
            float mx = tmp[0];
#pragma unroll
            for (int j = 1; j < 16; j++) mx = fmaxf(mx, tmp[j]);
            float ssum = 0.f;
#pragma unroll
            for (int j = 0; j < 16; j++) ssum += __expf(tmp[j] - mx);
            w = mx + __logf(ssum);
            Wsv[s * 16 + lane] = w;
        }
    }
}

// ---------------------------------------------------------------------------
// Scan pass 2: expand alpha/beta inside each chunk.
// ---------------------------------------------------------------------------
__global__ void pass2_kernel(const float* __restrict__ trs,
                             const float* __restrict__ pis,
                             const float* __restrict__ P,
                             const float* __restrict__ Suf,
                             const float* __restrict__ Vs,
                             const float* __restrict__ Wsv,
                             float* __restrict__ out_alpha,
                             float* __restrict__ out_beta)
{
    const int lane = threadIdx.x;
    if (lane >= 16) return;
    const unsigned mask = 0xFFFFu;
    const int b = blockIdx.x;

    if (b < G_CHUNKS) {   // forward
        const int g  = b;
        const int s  = g >> 4;
        const int r  = g & 15;
        const int t0 = g * CHUNK;
        const int t1 = min(t0 + CHUNK, NTRANS);

        float v;
        {
            float vs = Vs[s * 16 + lane];
            if (r == 0) {
                v = vs;
            } else {
                const float* Pm = P + (s * 16 + (r - 1)) * 256;
                float tmp[16];
#pragma unroll
                for (int i = 0; i < 16; i++)
                    tmp[i] = __shfl_sync(mask, vs, i) + Pm[i * 16 + lane];
                float mx = tmp[0];
#pragma unroll
                for (int i = 1; i < 16; i++) mx = fmaxf(mx, tmp[i]);
                float ssum = 0.f;
#pragma unroll
                for (int i = 0; i < 16; i++) ssum += __expf(tmp[i] - mx);
                v = mx + __logf(ssum);
            }
        }
        if (g == 0) out_alpha[lane] = v;

        for (int t = t0; t < t1; t++) {
            const float* M = trs + (size_t)t * 256;
            float tmp[16];
#pragma unroll
            for (int i = 0; i < 16; i++)
                tmp[i] = __shfl_sync(mask, v, i) + M[i * 16 + lane];
            float mx = tmp[0];
#pragma unroll
            for (int i = 1; i < 16; i++) mx = fmaxf(mx, tmp[i]);
            float ssum = 0.f;
#pragma unroll
            for (int i = 0; i < 16; i++) ssum += __expf(tmp[i] - mx);
            v = mx + __logf(ssum) + pis[(size_t)(t + 1) * 16 + lane];
            out_alpha[(size_t)(t + 1) * 16 + lane] = v;
        }
    } else {              // backward
        const int g  = b - G_CHUNKS;
        const int s  = g >> 4;
        const int r  = g & 15;
        const int t0 = g * CHUNK;
        const int t1 = min(t0 + CHUNK, NTRANS);

        float w;
        {
            float wsv = Wsv[(s + 1) * 16 + lane];
            if (r == 15) {
                w = wsv;
            } else {
                const float* Sf = Suf + (s * 16 + (r + 1)) * 256 + lane * 16;
                float tmp[16];
#pragma unroll
                for (int j = 0; j < 16; j++)
                    tmp[j] = Sf[j] + __shfl_sync(mask, wsv, j);
                float mx = tmp[0];
#pragma unroll
                for (int j = 1; j < 16; j++) mx = fmaxf(mx, tmp[j]);
                float ssum = 0.f;
#pragma unroll
                for (int j = 0; j < 16; j++) ssum += __expf(tmp[j] - mx);
                w = mx + __logf(ssum);
            }
        }

        for (int t = t1 - 1; t >= t0; t--) {
            const float* M = trs + (size_t)t * 256 + lane * 16;
            float u = w + pis[(size_t)(t + 1) * 16 + lane];
            float tmp[16];
#pragma unroll
            for (int j = 0; j < 16; j++)
                tmp[j] = __shfl_sync(mask, u, j) + M[j];
            float mx = tmp[0];
#pragma unroll
            for (int j = 1; j < 16; j++) mx = fmaxf(mx, tmp[j]);
            float ssum = 0.f;
#pragma unroll
            for (int j = 0; j < 16; j++) ssum += __expf(tmp[j] - mx);
            w = mx + __logf(ssum);
            out_beta[(size_t)t * 16 + lane] = w;
        }
    }
}

// ---------------------------------------------------------------------------
// Host launcher
// ---------------------------------------------------------------------------
extern "C" void kernel_launch(void* const* d_in, const int* in_sizes, int n_in,
                              void* d_out, int out_size)
{
    const float* s_arr = (const float*)d_in[0];
    const float* a_arr = (const float*)d_in[1];
    const float* pW1 = (const float*)d_in[2];  const float* pb1 = (const float*)d_in[3];
    const float* pW2 = (const float*)d_in[4];  const float* pb2 = (const float*)d_in[5];
    const float* pW3 = (const float*)d_in[6];  const float* pb3 = (const float*)d_in[7];
    const float* oW1 = (const float*)d_in[8];  const float* ob1 = (const float*)d_in[9];
    const float* oW2 = (const float*)d_in[10]; const float* ob2 = (const float*)d_in[11];
    const float* oW3 = (const float*)d_in[12]; const float* ob3 = (const float*)d_in[13];
    const float* als = (const float*)d_in[14];

    float* out = (float*)d_out;
    float* out_alpha = out + OFF_ALPHA;
    float* out_beta  = out + OFF_BETA;
    float* out_trs   = out + OFF_TRS;
    float* out_pis   = out + OFF_PIS;
    float* out_ent   = out + OFF_ENT;

    float *h1p, *h1o, *h2p, *h2o, *meanb, *logitsb, *Cmat, *Pm, *Sf, *Vs, *Wsv, *tr0;
    cudaGetSymbolAddress((void**)&h1p,    g_h1p);
    cudaGetSymbolAddress((void**)&h1o,    g_h1o);
    cudaGetSymbolAddress((void**)&h2p,    g_h2p);
    cudaGetSymbolAddress((void**)&h2o,    g_h2o);
    cudaGetSymbolAddress((void**)&meanb,  g_mean);
    cudaGetSymbolAddress((void**)&logitsb,g_logits);
    cudaGetSymbolAddress((void**)&Cmat,   g_Cmat);
    cudaGetSymbolAddress((void**)&Pm,     g_P);
    cudaGetSymbolAddress((void**)&Sf,     g_Suf);
    cudaGetSymbolAddress((void**)&Vs,     g_Vs);
    cudaGetSymbolAddress((void**)&Wsv,    g_Wsv);
    cudaGetSymbolAddress((void**)&tr0,    g_tr0);

    const int MB = T_LEN / 128;   // 512 row tiles

    // Layer 1 (both MLPs fused via blockIdx.z)
    gemm_tc<64, 256, true ><<<dim3(MB, 2, 2), 256>>>(
        s_arr, pW1, pb1, h1p,  s_arr, oW1, ob1, h1o);
    // Layer 2 (both MLPs fused)
    gemm_tc<256, 256, true ><<<dim3(MB, 2, 2), 256>>>(
        h1p, pW2, pb2, h2p,  h1o, oW2, ob2, h2o);
    // Layer 3 (different N -> separate launches)
    gemm_tc<256, 128, false><<<dim3(MB, 1, 1), 256>>>(
        h2p, pW3, pb3, meanb,  h2p, pW3, pb3, meanb);
    gemm_tc<256, 272, false><<<dim3(MB, 3, 1), 256>>>(
        h2o, oW3, ob3, logitsb,  h2o, oW3, ob3, logitsb);

    // Post-processing
    logpis_kernel<<<(T_LEN * DIM_C + 255) / 256, 256>>>(meanb, a_arr, als, out_pis);
    softmax_kernel<<<(T_LEN * 17 + 255) / 256, 256>>>(logitsb, out_trs, out_ent, tr0);

    // Parallel log-semiring scans
    pass1_kernel<<<G_CHUNKS, 256>>>(out_trs, out_pis, Cmat);
    superprod_kernel<<<2 * NSUPER, 256>>>(Cmat, Pm, Sf);
    combine2_kernel<<<2, 32>>>(Pm, tr0, out_pis, Vs, Wsv, out_beta);
    pass2_kernel<<<2 * G_CHUNKS, 32>>>(out_trs, out_pis, Pm, Sf, Vs, Wsv,
                                       out_alpha, out_beta);
}